// round 1
// baseline (speedup 1.0000x reference)
#include <cuda_runtime.h>
#include <cstdint>

// ---------------------------------------------------------------------------
// Problem constants
//   B=128, T_V=64, T_A=128, E_V=1024, E_A=512, H=1024, EMB=512, C=512
//   IN=1024, VOCAB=20000
// Output = [logits(128*20000) | h_new(128*1024) | c_new(128*1024)]
// ---------------------------------------------------------------------------

#define BM 64
#define BN 64
#define BKK 16

// Scratch offsets (floats)
#define OFF_V2V     0u            // 8192*512      = 4194304
#define OFF_V2A     4194304u      // 16384*512     = 8388608
#define OFF_V1V     12582912u     // 128*512
#define OFF_V1A     12648448u     // 128*512
#define OFF_V1C     12713984u     // 128*512
#define OFF_CTXV    12779520u     // 128*1024
#define OFF_CTXA    12910592u     // 128*512
#define OFF_ALLCTX  12976128u     // 128*2*512
#define OFF_V2C     13107200u     // 256*512
#define OFF_X       13238272u     // 128*1024
#define OFF_GATES   13369344u     // 128*4096
#define OFF_H       13893632u     // 128*1024
#define SCRATCH_FLOATS 14024704u

__device__ float g_scratch[SCRATCH_FLOATS];

// ---------------------------------------------------------------------------
// Generic tiled GEMM:  C[M,N] (+)= A[M,K] @ B[N,K]^T  (+ bias[n])
// A row stride = lda, B row stride = ldb, C row stride = ldc.
// Requires: M % 64 == 0 (true for all call sites), K % 16 == 0,
//           A/B 16B-aligned with lda/ldb % 4 == 0. N may be ragged (guarded).
// ---------------------------------------------------------------------------
__global__ void __launch_bounds__(256) gemm_tn(
    const float* __restrict__ A, int lda,
    const float* __restrict__ B, int ldb,
    const float* __restrict__ bias,
    float* __restrict__ C, int ldc,
    int M, int N, int K, int accum)
{
    __shared__ __align__(16) float As[BKK][BM + 4];
    __shared__ __align__(16) float Bs[BKK][BN + 4];

    const int tid = threadIdx.x;
    const int tx = tid & 15;       // 0..15 -> N direction (4 cols each)
    const int ty = tid >> 4;       // 0..15 -> M direction (4 rows each)
    const int mBase = blockIdx.y * BM;
    const int nBase = blockIdx.x * BN;

    const int r  = tid >> 2;              // 0..63 tile row for loading
    const int kq = (tid & 3) << 2;        // 0,4,8,12 k-offset (float4)

    float acc[4][4];
#pragma unroll
    for (int i = 0; i < 4; i++)
#pragma unroll
        for (int j = 0; j < 4; j++) acc[i][j] = 0.f;

    const float* Aptr = A + (size_t)(mBase + r) * lda + kq;
    const int nrow = nBase + r;
    const float* Bptr = B + (size_t)nrow * ldb + kq;
    const bool bok = (nrow < N);

    for (int k0 = 0; k0 < K; k0 += BKK) {
        float4 a4 = *(const float4*)(Aptr + k0);
        float4 b4 = bok ? *(const float4*)(Bptr + k0)
                        : make_float4(0.f, 0.f, 0.f, 0.f);
        As[kq + 0][r] = a4.x; As[kq + 1][r] = a4.y;
        As[kq + 2][r] = a4.z; As[kq + 3][r] = a4.w;
        Bs[kq + 0][r] = b4.x; Bs[kq + 1][r] = b4.y;
        Bs[kq + 2][r] = b4.z; Bs[kq + 3][r] = b4.w;
        __syncthreads();

#pragma unroll
        for (int kk = 0; kk < BKK; kk++) {
            float4 av = *(const float4*)(&As[kk][ty << 2]);
            float4 bv = *(const float4*)(&Bs[kk][tx << 2]);
            float a[4] = {av.x, av.y, av.z, av.w};
            float b[4] = {bv.x, bv.y, bv.z, bv.w};
#pragma unroll
            for (int i = 0; i < 4; i++)
#pragma unroll
                for (int j = 0; j < 4; j++)
                    acc[i][j] += a[i] * b[j];
        }
        __syncthreads();
    }

#pragma unroll
    for (int i = 0; i < 4; i++) {
        const int m = mBase + (ty << 2) + i;
        if (m >= M) continue;
#pragma unroll
        for (int j = 0; j < 4; j++) {
            const int n = nBase + (tx << 2) + j;
            if (n >= N) continue;
            float v = acc[i][j];
            if (bias) v += bias[n];
            if (accum) C[(size_t)m * ldc + n] += v;
            else       C[(size_t)m * ldc + n]  = v;
        }
    }
}

// ---------------------------------------------------------------------------
// Bahdanau attention finish: scores = tanh(v1+v2)@W3, softmax over T,
// ctx = attn @ enc.  One block per batch element.
// ---------------------------------------------------------------------------
__global__ void __launch_bounds__(256) attend_kernel(
    const float* __restrict__ v1,   // [B,C]
    const float* __restrict__ v2,   // [B,T,C]
    const float* __restrict__ W3,   // [C]
    const float* __restrict__ enc,  // [B,T,E]
    float* __restrict__ ctx,        // [B,E]
    int T, int C, int E)
{
    const int b = blockIdx.x;
    const int tid = threadIdx.x;
    const int warp = tid >> 5, lane = tid & 31;
    __shared__ float s_sc[128];
    __shared__ float s_inv;

    const float* v1b = v1 + (size_t)b * C;
    const float* v2b = v2 + (size_t)b * T * C;

    for (int t = warp; t < T; t += 8) {
        const float* row = v2b + (size_t)t * C;
        float acc = 0.f;
        for (int c = lane; c < C; c += 32)
            acc += tanhf(v1b[c] + row[c]) * W3[c];
#pragma unroll
        for (int o = 16; o; o >>= 1) acc += __shfl_xor_sync(0xffffffffu, acc, o);
        if (lane == 0) s_sc[t] = acc;
    }
    __syncthreads();

    if (tid == 0) {
        float m = -1e30f;
        for (int t = 0; t < T; t++) m = fmaxf(m, s_sc[t]);
        float s = 0.f;
        for (int t = 0; t < T; t++) { float e = expf(s_sc[t] - m); s_sc[t] = e; s += e; }
        s_inv = 1.f / s;
    }
    __syncthreads();
    const float inv = s_inv;

    const float* encb = enc + (size_t)b * T * E;
    for (int e = tid; e < E; e += 256) {
        float acc = 0.f;
        for (int t = 0; t < T; t++) acc += s_sc[t] * encb[(size_t)t * E + e];
        ctx[(size_t)b * E + e] = acc * inv;
    }
}

// ---------------------------------------------------------------------------
// Cross-modal attention (T=2) + final context + x = [input, tanh(final_ctx)]
// One block per batch element.
// ---------------------------------------------------------------------------
__global__ void __launch_bounds__(256) ca_finish_kernel(
    const float* __restrict__ v1c,    // [B,512]
    const float* __restrict__ v2c,    // [B*2,512]
    const float* __restrict__ W3,     // [512]
    const float* __restrict__ allctx, // [B,2,512]
    const float* __restrict__ inp,    // [B,512]
    float* __restrict__ x)            // [B,1024]
{
    const int C = 512, EMB = 512;
    const int b = blockIdx.x;
    const int tid = threadIdx.x;
    const int warp = tid >> 5, lane = tid & 31;
    __shared__ float red0[8], red1[8];
    __shared__ float s_a0, s_a1;

    const float* v1b = v1c + (size_t)b * C;
    const float* v20 = v2c + (size_t)(2 * b) * C;
    const float* v21 = v20 + C;

    float p0 = 0.f, p1 = 0.f;
    for (int c = tid; c < C; c += 256) {
        const float w = W3[c];
        p0 += tanhf(v1b[c] + v20[c]) * w;
        p1 += tanhf(v1b[c] + v21[c]) * w;
    }
#pragma unroll
    for (int o = 16; o; o >>= 1) {
        p0 += __shfl_xor_sync(0xffffffffu, p0, o);
        p1 += __shfl_xor_sync(0xffffffffu, p1, o);
    }
    if (lane == 0) { red0[warp] = p0; red1[warp] = p1; }
    __syncthreads();
    if (tid == 0) {
        float s0 = 0.f, s1 = 0.f;
        for (int w = 0; w < 8; w++) { s0 += red0[w]; s1 += red1[w]; }
        const float m = fmaxf(s0, s1);
        const float e0 = expf(s0 - m), e1 = expf(s1 - m);
        const float inv = 1.f / (e0 + e1);
        s_a0 = e0 * inv; s_a1 = e1 * inv;
    }
    __syncthreads();
    const float a0 = s_a0, a1 = s_a1;

    const float* ctx0 = allctx + (size_t)b * 2 * C;
    const float* ctx1 = ctx0 + C;
    float* xb = x + (size_t)b * (EMB + C);
    const float* ib = inp + (size_t)b * EMB;
    for (int e = tid; e < EMB; e += 256) xb[e] = ib[e];
    for (int c = tid; c < C; c += 256)
        xb[EMB + c] = tanhf(a0 * ctx0[c] + a1 * ctx1[c]);
}

// ---------------------------------------------------------------------------
// LSTM pointwise: gates[B,4H] (+ biases) -> h_new, c_new
// ---------------------------------------------------------------------------
__global__ void __launch_bounds__(256) lstm_kernel(
    const float* __restrict__ gates,
    const float* __restrict__ b_ih, const float* __restrict__ b_hh,
    const float* __restrict__ c0,
    float* __restrict__ h_scratch,
    float* __restrict__ h_out, float* __restrict__ c_out)
{
    const int idx = blockIdx.x * 256 + threadIdx.x;  // < 128*1024
    const int b = idx >> 10, k = idx & 1023;
    const float* g = gates + (size_t)b * 4096;

    const float ig = g[k]        + b_ih[k]        + b_hh[k];
    const float fg = g[1024 + k] + b_ih[1024 + k] + b_hh[1024 + k];
    const float gg = g[2048 + k] + b_ih[2048 + k] + b_hh[2048 + k];
    const float og = g[3072 + k] + b_ih[3072 + k] + b_hh[3072 + k];

    const float si = 1.f / (1.f + expf(-ig));
    const float sf = 1.f / (1.f + expf(-fg));
    const float so = 1.f / (1.f + expf(-og));
    const float cn = sf * c0[idx] + si * tanhf(gg);
    const float hn = so * tanhf(cn);

    h_scratch[idx] = hn;
    h_out[idx] = hn;
    c_out[idx] = cn;
}

// ---------------------------------------------------------------------------
// Launch
// ---------------------------------------------------------------------------
extern "C" void kernel_launch(void* const* d_in, const int* in_sizes, int n_in,
                              void* d_out, int out_size)
{
    (void)in_sizes; (void)n_in; (void)out_size;

    float* S = nullptr;
    cudaGetSymbolAddress((void**)&S, g_scratch);

    const float* input  = (const float*)d_in[0];   // [128,1,512]
    const float* enc_v  = (const float*)d_in[1];   // [128,64,1024]
    const float* enc_a  = (const float*)d_in[2];   // [128,128,512]
    const float* h0     = (const float*)d_in[3];   // [1,128,1024]
    const float* c0     = (const float*)d_in[4];   // [1,128,1024]
    const float* W_va1  = (const float*)d_in[5];   // [512,1024]
    const float* W_va2  = (const float*)d_in[6];   // [512,1024]
    const float* W_va3  = (const float*)d_in[7];   // [1,512]
    const float* W_venc = (const float*)d_in[8];   // [512,1024]
    const float* W_aa1  = (const float*)d_in[9];   // [512,1024]
    const float* W_aa2  = (const float*)d_in[10];  // [512,512]
    const float* W_aa3  = (const float*)d_in[11];  // [1,512]
    const float* W_aenc = (const float*)d_in[12];  // [512,512]
    const float* W_ca1  = (const float*)d_in[13];  // [512,1024]
    const float* W_ca2  = (const float*)d_in[14];  // [512,512]
    const float* W_ca3  = (const float*)d_in[15];  // [1,512]
    const float* W_ih   = (const float*)d_in[16];  // [4096,1024]
    const float* W_hh   = (const float*)d_in[17];  // [4096,1024]
    const float* b_ih   = (const float*)d_in[18];  // [4096]
    const float* b_hh   = (const float*)d_in[19];  // [4096]
    const float* W_out  = (const float*)d_in[20];  // [20000,1024]
    const float* b_out  = (const float*)d_in[21];  // [20000]

    float* out    = (float*)d_out;
    float* logits = out;                       // 128*20000
    float* h_out  = out + 128 * 20000;         // 128*1024
    float* c_out  = h_out + 128 * 1024;        // 128*1024

    float* v2v    = S + OFF_V2V;
    float* v2a    = S + OFF_V2A;
    float* v1v    = S + OFF_V1V;
    float* v1a    = S + OFF_V1A;
    float* v1c    = S + OFF_V1C;
    float* ctxv   = S + OFF_CTXV;
    float* ctxa   = S + OFF_CTXA;
    float* allctx = S + OFF_ALLCTX;
    float* v2c    = S + OFF_V2C;
    float* x      = S + OFF_X;
    float* gates  = S + OFF_GATES;
    float* hsc    = S + OFF_H;

    dim3 blk(256);
    auto G = [](int M, int N) {
        return dim3((unsigned)((N + BN - 1) / BN), (unsigned)((M + BM - 1) / BM));
    };

    // h-dependent projections for the three attentions
    gemm_tn<<<G(128, 512), blk>>>(h0, 1024, W_va1, 1024, nullptr, v1v, 512, 128, 512, 1024, 0);
    gemm_tn<<<G(128, 512), blk>>>(h0, 1024, W_aa1, 1024, nullptr, v1a, 512, 128, 512, 1024, 0);
    gemm_tn<<<G(128, 512), blk>>>(h0, 1024, W_ca1, 1024, nullptr, v1c, 512, 128, 512, 1024, 0);

    // encoder projections (the two biggest GEMMs)
    gemm_tn<<<G(8192, 512), blk>>>(enc_v, 1024, W_va2, 1024, nullptr, v2v, 512, 8192, 512, 1024, 0);
    gemm_tn<<<G(16384, 512), blk>>>(enc_a, 512, W_aa2, 512, nullptr, v2a, 512, 16384, 512, 512, 0);

    // attention + context
    attend_kernel<<<128, blk>>>(v1v, v2v, W_va3, enc_v, ctxv, 64, 512, 1024);
    attend_kernel<<<128, blk>>>(v1a, v2a, W_aa3, enc_a, ctxa, 128, 512, 512);

    // vc/ac projected, interleaved into all_ctx[B,2,C]
    gemm_tn<<<G(128, 512), blk>>>(ctxv, 1024, W_venc, 1024, nullptr, allctx, 1024, 128, 512, 1024, 0);
    gemm_tn<<<G(128, 512), blk>>>(ctxa, 512, W_aenc, 512, nullptr, allctx + 512, 1024, 128, 512, 512, 0);

    // cross-modal v2 as one GEMM over the 256 stacked context rows
    gemm_tn<<<G(256, 512), blk>>>(allctx, 512, W_ca2, 512, nullptr, v2c, 512, 256, 512, 512, 0);

    // softmax over 2, final context, x = [input, tanh(ctx)]
    ca_finish_kernel<<<128, blk>>>(v1c, v2c, W_ca3, allctx, input, x);

    // LSTM gates: x@W_ih^T then += h0@W_hh^T
    gemm_tn<<<G(128, 4096), blk>>>(x, 1024, W_ih, 1024, nullptr, gates, 4096, 128, 4096, 1024, 0);
    gemm_tn<<<G(128, 4096), blk>>>(h0, 1024, W_hh, 1024, nullptr, gates, 4096, 128, 4096, 1024, 1);

    // pointwise LSTM -> h_new, c_new (into d_out + scratch)
    lstm_kernel<<<512, blk>>>(gates, b_ih, b_hh, c0, hsc, h_out, c_out);

    // output projection
    gemm_tn<<<G(128, 20000), blk>>>(hsc, 1024, W_out, 1024, b_out, logits, 20000, 128, 20000, 1024, 0);
}

// round 2
// speedup vs baseline: 1.9506x; 1.9506x over previous
#include <cuda_runtime.h>
#include <cstdint>

// ---------------------------------------------------------------------------
// Problem constants
//   B=128, T_V=64, T_A=128, E_V=1024, E_A=512, H=1024, EMB=512, C=512
//   IN=1024, VOCAB=20000
// Output = [logits(128*20000) | h_new(128*1024) | c_new(128*1024)]
// ---------------------------------------------------------------------------

// Scratch offsets (floats)
#define OFF_V2V     0u            // 8192*512      = 4194304
#define OFF_V2A     4194304u      // 16384*512     = 8388608
#define OFF_V1V     12582912u     // 128*512
#define OFF_V1A     12648448u     // 128*512
#define OFF_V1C     12713984u     // 128*512
#define OFF_CTXV    12779520u     // 128*1024
#define OFF_CTXA    12910592u     // 128*512
#define OFF_ALLCTX  12976128u     // 128*2*512
#define OFF_V2C     13107200u     // 256*512
#define OFF_X       13238272u     // 128*1024
#define OFF_GATES   13369344u     // 128*4096
#define OFF_H       13893632u     // 128*1024
#define SCRATCH_FLOATS 14024704u

__device__ float g_scratch[SCRATCH_FLOATS];

__device__ __forceinline__ uint32_t f2tf(float f) {
    uint32_t u;
    asm("cvt.rna.tf32.f32 %0, %1;" : "=r"(u) : "f"(f));
    return u;
}

// ---------------------------------------------------------------------------
// TF32 tensor-core GEMM:  C[M,N] (+)= A[M,K] @ B[N,K]^T  (+ bias[n])
// Requires: M % 64 == 0, K % 32 == 0, A/B rows 16B-aligned (lda/ldb % 4 == 0).
// N may be ragged (guarded on B loads and C stores).
// Tile 64x64x32, 128 threads = 4 warps (2x2), warp tile 32x32.
// mma.sync.aligned.m16n8k8 tf32, fp32 accumulate.
// ---------------------------------------------------------------------------
__global__ void __launch_bounds__(128) gemm_tc(
    const float* __restrict__ A, int lda,
    const float* __restrict__ B, int ldb,
    const float* __restrict__ bias,
    float* __restrict__ C, int ldc,
    int M, int N, int K, int accum)
{
    __shared__ uint32_t As[64][36];   // padded: (36r+c)%32=(4r+c)%32 -> conflict-free frags
    __shared__ uint32_t Bs[64][36];

    const int tid  = threadIdx.x;
    const int lane = tid & 31;
    const int warp = tid >> 5;
    const int wm = warp >> 1;         // 0..1
    const int wn = warp & 1;          // 0..1
    const int mBase = blockIdx.y << 6;
    const int nBase = blockIdx.x << 6;

    const int lr = tid >> 3;          // 0..15  (smem-load row group)
    const int lc = tid & 7;           // 0..7   (float4 column)

    float acc[2][4][4];
#pragma unroll
    for (int i = 0; i < 2; i++)
#pragma unroll
        for (int j = 0; j < 4; j++)
#pragma unroll
            for (int k = 0; k < 4; k++) acc[i][j][k] = 0.f;

    const int nk = K >> 5;
    float4 pa[4], pb[4];

    // ---- load k-tile 0 into registers ----
    {
        const float* Ap = A + (size_t)(mBase + lr) * lda + (lc << 2);
#pragma unroll
        for (int i = 0; i < 4; i++)
            pa[i] = *(const float4*)(Ap + (size_t)(i * 16) * lda);
#pragma unroll
        for (int i = 0; i < 4; i++) {
            const int nr = nBase + lr + i * 16;
            pb[i] = (nr < N) ? *(const float4*)(B + (size_t)nr * ldb + (lc << 2))
                             : make_float4(0.f, 0.f, 0.f, 0.f);
        }
    }
    // ---- store k-tile 0 to smem (with tf32 rounding) ----
#pragma unroll
    for (int i = 0; i < 4; i++) {
        const int r = lr + (i << 4);
        uint4 v;
        v.x = f2tf(pa[i].x); v.y = f2tf(pa[i].y); v.z = f2tf(pa[i].z); v.w = f2tf(pa[i].w);
        *(uint4*)&As[r][lc << 2] = v;
        uint4 w;
        w.x = f2tf(pb[i].x); w.y = f2tf(pb[i].y); w.z = f2tf(pb[i].z); w.w = f2tf(pb[i].w);
        *(uint4*)&Bs[r][lc << 2] = w;
    }

    for (int kt = 0; kt < nk; kt++) {
        __syncthreads();

        const bool more = (kt + 1 < nk);
        if (more) {
            const int ko = (kt + 1) << 5;
            const float* Ap = A + (size_t)(mBase + lr) * lda + ko + (lc << 2);
#pragma unroll
            for (int i = 0; i < 4; i++)
                pa[i] = *(const float4*)(Ap + (size_t)(i * 16) * lda);
#pragma unroll
            for (int i = 0; i < 4; i++) {
                const int nr = nBase + lr + i * 16;
                pb[i] = (nr < N)
                    ? *(const float4*)(B + (size_t)nr * ldb + ko + (lc << 2))
                    : make_float4(0.f, 0.f, 0.f, 0.f);
            }
        }

#pragma unroll
        for (int kk = 0; kk < 32; kk += 8) {
            uint32_t a[2][4], b[4][2];
#pragma unroll
            for (int im = 0; im < 2; im++) {
                const int r = (wm << 5) + (im << 4) + (lane >> 2);
                const int c = kk + (lane & 3);
                a[im][0] = As[r][c];
                a[im][1] = As[r + 8][c];
                a[im][2] = As[r][c + 4];
                a[im][3] = As[r + 8][c + 4];
            }
#pragma unroll
            for (int jn = 0; jn < 4; jn++) {
                const int nr = (wn << 5) + (jn << 3) + (lane >> 2);
                const int c = kk + (lane & 3);
                b[jn][0] = Bs[nr][c];
                b[jn][1] = Bs[nr][c + 4];
            }
#pragma unroll
            for (int im = 0; im < 2; im++)
#pragma unroll
                for (int jn = 0; jn < 4; jn++)
                    asm volatile(
                        "mma.sync.aligned.m16n8k8.row.col.f32.tf32.tf32.f32 "
                        "{%0,%1,%2,%3}, {%4,%5,%6,%7}, {%8,%9}, {%0,%1,%2,%3};"
                        : "+f"(acc[im][jn][0]), "+f"(acc[im][jn][1]),
                          "+f"(acc[im][jn][2]), "+f"(acc[im][jn][3])
                        : "r"(a[im][0]), "r"(a[im][1]), "r"(a[im][2]), "r"(a[im][3]),
                          "r"(b[jn][0]), "r"(b[jn][1]));
        }

        __syncthreads();
        if (more) {
#pragma unroll
            for (int i = 0; i < 4; i++) {
                const int r = lr + (i << 4);
                uint4 v;
                v.x = f2tf(pa[i].x); v.y = f2tf(pa[i].y); v.z = f2tf(pa[i].z); v.w = f2tf(pa[i].w);
                *(uint4*)&As[r][lc << 2] = v;
                uint4 w;
                w.x = f2tf(pb[i].x); w.y = f2tf(pb[i].y); w.z = f2tf(pb[i].z); w.w = f2tf(pb[i].w);
                *(uint4*)&Bs[r][lc << 2] = w;
            }
        }
    }

    // ---- epilogue ----
#pragma unroll
    for (int im = 0; im < 2; im++) {
        const int m0 = mBase + (wm << 5) + (im << 4) + (lane >> 2);
#pragma unroll
        for (int jn = 0; jn < 4; jn++) {
            const int n0 = nBase + (wn << 5) + (jn << 3) + ((lane & 3) << 1);
#pragma unroll
            for (int half = 0; half < 2; half++) {
                const int m = m0 + half * 8;
                const float v0 = acc[im][jn][half * 2 + 0];
                const float v1 = acc[im][jn][half * 2 + 1];
                if (n0 < N) {
                    float x = v0 + (bias ? bias[n0] : 0.f);
                    if (accum) C[(size_t)m * ldc + n0] += x;
                    else       C[(size_t)m * ldc + n0]  = x;
                }
                if (n0 + 1 < N) {
                    float x = v1 + (bias ? bias[n0 + 1] : 0.f);
                    if (accum) C[(size_t)m * ldc + n0 + 1] += x;
                    else       C[(size_t)m * ldc + n0 + 1]  = x;
                }
            }
        }
    }
}

// ---------------------------------------------------------------------------
// Bahdanau attention finish: scores = tanh(v1+v2)@W3, softmax over T,
// ctx = attn @ enc.  One block per batch element.
// ---------------------------------------------------------------------------
__global__ void __launch_bounds__(256) attend_kernel(
    const float* __restrict__ v1,   // [B,C]
    const float* __restrict__ v2,   // [B,T,C]
    const float* __restrict__ W3,   // [C]
    const float* __restrict__ enc,  // [B,T,E]
    float* __restrict__ ctx,        // [B,E]
    int T, int C, int E)
{
    const int b = blockIdx.x;
    const int tid = threadIdx.x;
    const int warp = tid >> 5, lane = tid & 31;
    __shared__ float s_sc[128];
    __shared__ float s_inv;

    const float* v1b = v1 + (size_t)b * C;
    const float* v2b = v2 + (size_t)b * T * C;

    for (int t = warp; t < T; t += 8) {
        const float* row = v2b + (size_t)t * C;
        float acc = 0.f;
        for (int c = lane; c < C; c += 32)
            acc += tanhf(v1b[c] + row[c]) * W3[c];
#pragma unroll
        for (int o = 16; o; o >>= 1) acc += __shfl_xor_sync(0xffffffffu, acc, o);
        if (lane == 0) s_sc[t] = acc;
    }
    __syncthreads();

    if (tid == 0) {
        float m = -1e30f;
        for (int t = 0; t < T; t++) m = fmaxf(m, s_sc[t]);
        float s = 0.f;
        for (int t = 0; t < T; t++) { float e = expf(s_sc[t] - m); s_sc[t] = e; s += e; }
        s_inv = 1.f / s;
    }
    __syncthreads();
    const float inv = s_inv;

    const float* encb = enc + (size_t)b * T * E;
    for (int e = tid; e < E; e += 256) {
        float acc = 0.f;
        for (int t = 0; t < T; t++) acc += s_sc[t] * encb[(size_t)t * E + e];
        ctx[(size_t)b * E + e] = acc * inv;
    }
}

// ---------------------------------------------------------------------------
// Cross-modal attention (T=2) + final context + x = [input, tanh(final_ctx)]
// ---------------------------------------------------------------------------
__global__ void __launch_bounds__(256) ca_finish_kernel(
    const float* __restrict__ v1c,    // [B,512]
    const float* __restrict__ v2c,    // [B*2,512]
    const float* __restrict__ W3,     // [512]
    const float* __restrict__ allctx, // [B,2,512]
    const float* __restrict__ inp,    // [B,512]
    float* __restrict__ x)            // [B,1024]
{
    const int C = 512, EMB = 512;
    const int b = blockIdx.x;
    const int tid = threadIdx.x;
    const int warp = tid >> 5, lane = tid & 31;
    __shared__ float red0[8], red1[8];
    __shared__ float s_a0, s_a1;

    const float* v1b = v1c + (size_t)b * C;
    const float* v20 = v2c + (size_t)(2 * b) * C;
    const float* v21 = v20 + C;

    float p0 = 0.f, p1 = 0.f;
    for (int c = tid; c < C; c += 256) {
        const float w = W3[c];
        p0 += tanhf(v1b[c] + v20[c]) * w;
        p1 += tanhf(v1b[c] + v21[c]) * w;
    }
#pragma unroll
    for (int o = 16; o; o >>= 1) {
        p0 += __shfl_xor_sync(0xffffffffu, p0, o);
        p1 += __shfl_xor_sync(0xffffffffu, p1, o);
    }
    if (lane == 0) { red0[warp] = p0; red1[warp] = p1; }
    __syncthreads();
    if (tid == 0) {
        float s0 = 0.f, s1 = 0.f;
        for (int w = 0; w < 8; w++) { s0 += red0[w]; s1 += red1[w]; }
        const float m = fmaxf(s0, s1);
        const float e0 = expf(s0 - m), e1 = expf(s1 - m);
        const float inv = 1.f / (e0 + e1);
        s_a0 = e0 * inv; s_a1 = e1 * inv;
    }
    __syncthreads();
    const float a0 = s_a0, a1 = s_a1;

    const float* ctx0 = allctx + (size_t)b * 2 * C;
    const float* ctx1 = ctx0 + C;
    float* xb = x + (size_t)b * (EMB + C);
    const float* ib = inp + (size_t)b * EMB;
    for (int e = tid; e < EMB; e += 256) xb[e] = ib[e];
    for (int c = tid; c < C; c += 256)
        xb[EMB + c] = tanhf(a0 * ctx0[c] + a1 * ctx1[c]);
}

// ---------------------------------------------------------------------------
// LSTM pointwise: gates[B,4H] (+ biases) -> h_new, c_new
// ---------------------------------------------------------------------------
__global__ void __launch_bounds__(256) lstm_kernel(
    const float* __restrict__ gates,
    const float* __restrict__ b_ih, const float* __restrict__ b_hh,
    const float* __restrict__ c0,
    float* __restrict__ h_scratch,
    float* __restrict__ h_out, float* __restrict__ c_out)
{
    const int idx = blockIdx.x * 256 + threadIdx.x;  // < 128*1024
    const int b = idx >> 10, k = idx & 1023;
    const float* g = gates + (size_t)b * 4096;

    const float ig = g[k]        + b_ih[k]        + b_hh[k];
    const float fg = g[1024 + k] + b_ih[1024 + k] + b_hh[1024 + k];
    const float gg = g[2048 + k] + b_ih[2048 + k] + b_hh[2048 + k];
    const float og = g[3072 + k] + b_ih[3072 + k] + b_hh[3072 + k];

    const float si = 1.f / (1.f + expf(-ig));
    const float sf = 1.f / (1.f + expf(-fg));
    const float so = 1.f / (1.f + expf(-og));
    const float cn = sf * c0[idx] + si * tanhf(gg);
    const float hn = so * tanhf(cn);

    h_scratch[idx] = hn;
    h_out[idx] = hn;
    c_out[idx] = cn;
}

// ---------------------------------------------------------------------------
// Launch
// ---------------------------------------------------------------------------
extern "C" void kernel_launch(void* const* d_in, const int* in_sizes, int n_in,
                              void* d_out, int out_size)
{
    (void)in_sizes; (void)n_in; (void)out_size;

    float* S = nullptr;
    cudaGetSymbolAddress((void**)&S, g_scratch);

    const float* input  = (const float*)d_in[0];   // [128,1,512]
    const float* enc_v  = (const float*)d_in[1];   // [128,64,1024]
    const float* enc_a  = (const float*)d_in[2];   // [128,128,512]
    const float* h0     = (const float*)d_in[3];   // [1,128,1024]
    const float* c0     = (const float*)d_in[4];   // [1,128,1024]
    const float* W_va1  = (const float*)d_in[5];   // [512,1024]
    const float* W_va2  = (const float*)d_in[6];   // [512,1024]
    const float* W_va3  = (const float*)d_in[7];   // [1,512]
    const float* W_venc = (const float*)d_in[8];   // [512,1024]
    const float* W_aa1  = (const float*)d_in[9];   // [512,1024]
    const float* W_aa2  = (const float*)d_in[10];  // [512,512]
    const float* W_aa3  = (const float*)d_in[11];  // [1,512]
    const float* W_aenc = (const float*)d_in[12];  // [512,512]
    const float* W_ca1  = (const float*)d_in[13];  // [512,1024]
    const float* W_ca2  = (const float*)d_in[14];  // [512,512]
    const float* W_ca3  = (const float*)d_in[15];  // [1,512]
    const float* W_ih   = (const float*)d_in[16];  // [4096,1024]
    const float* W_hh   = (const float*)d_in[17];  // [4096,1024]
    const float* b_ih   = (const float*)d_in[18];  // [4096]
    const float* b_hh   = (const float*)d_in[19];  // [4096]
    const float* W_out  = (const float*)d_in[20];  // [20000,1024]
    const float* b_out  = (const float*)d_in[21];  // [20000]

    float* out    = (float*)d_out;
    float* logits = out;                       // 128*20000
    float* h_out  = out + 128 * 20000;         // 128*1024
    float* c_out  = h_out + 128 * 1024;        // 128*1024

    float* v2v    = S + OFF_V2V;
    float* v2a    = S + OFF_V2A;
    float* v1v    = S + OFF_V1V;
    float* v1a    = S + OFF_V1A;
    float* v1c    = S + OFF_V1C;
    float* ctxv   = S + OFF_CTXV;
    float* ctxa   = S + OFF_CTXA;
    float* allctx = S + OFF_ALLCTX;
    float* v2c    = S + OFF_V2C;
    float* x      = S + OFF_X;
    float* gates  = S + OFF_GATES;
    float* hsc    = S + OFF_H;

    dim3 blk(128);
    auto G = [](int M, int N) {
        return dim3((unsigned)((N + 63) / 64), (unsigned)(M / 64));
    };

    // h-dependent projections for the three attentions
    gemm_tc<<<G(128, 512), blk>>>(h0, 1024, W_va1, 1024, nullptr, v1v, 512, 128, 512, 1024, 0);
    gemm_tc<<<G(128, 512), blk>>>(h0, 1024, W_aa1, 1024, nullptr, v1a, 512, 128, 512, 1024, 0);
    gemm_tc<<<G(128, 512), blk>>>(h0, 1024, W_ca1, 1024, nullptr, v1c, 512, 128, 512, 1024, 0);

    // encoder projections (the two biggest GEMMs)
    gemm_tc<<<G(8192, 512), blk>>>(enc_v, 1024, W_va2, 1024, nullptr, v2v, 512, 8192, 512, 1024, 0);
    gemm_tc<<<G(16384, 512), blk>>>(enc_a, 512, W_aa2, 512, nullptr, v2a, 512, 16384, 512, 512, 0);

    // attention + context
    attend_kernel<<<128, dim3(256)>>>(v1v, v2v, W_va3, enc_v, ctxv, 64, 512, 1024);
    attend_kernel<<<128, dim3(256)>>>(v1a, v2a, W_aa3, enc_a, ctxa, 128, 512, 512);

    // vc/ac projected, interleaved into all_ctx[B,2,C]
    gemm_tc<<<G(128, 512), blk>>>(ctxv, 1024, W_venc, 1024, nullptr, allctx, 1024, 128, 512, 1024, 0);
    gemm_tc<<<G(128, 512), blk>>>(ctxa, 512, W_aenc, 512, nullptr, allctx + 512, 1024, 128, 512, 512, 0);

    // cross-modal v2 as one GEMM over the 256 stacked context rows
    gemm_tc<<<G(256, 512), blk>>>(allctx, 512, W_ca2, 512, nullptr, v2c, 512, 256, 512, 512, 0);

    // softmax over 2, final context, x = [input, tanh(ctx)]
    ca_finish_kernel<<<128, dim3(256)>>>(v1c, v2c, W_ca3, allctx, input, x);

    // LSTM gates: x@W_ih^T then += h0@W_hh^T
    gemm_tc<<<G(128, 4096), blk>>>(x, 1024, W_ih, 1024, nullptr, gates, 4096, 128, 4096, 1024, 0);
    gemm_tc<<<G(128, 4096), blk>>>(h0, 1024, W_hh, 1024, nullptr, gates, 4096, 128, 4096, 1024, 1);

    // pointwise LSTM -> h_new, c_new (into d_out + scratch)
    lstm_kernel<<<512, dim3(256)>>>(gates, b_ih, b_hh, c0, hsc, h_out, c_out);

    // output projection
    gemm_tc<<<G(128, 20000), blk>>>(hsc, 1024, W_out, 1024, b_out, logits, 20000, 128, 20000, 1024, 0);
}

// round 3
// speedup vs baseline: 3.2647x; 1.6737x over previous
#include <cuda_runtime.h>
#include <cstdint>

// ---------------------------------------------------------------------------
// Problem constants
//   B=128, T_V=64, T_A=128, E_V=1024, E_A=512, H=1024, EMB=512, C=512
//   IN=1024, VOCAB=20000
// Output = [logits(128*20000) | h_new(128*1024) | c_new(128*1024)]
// ---------------------------------------------------------------------------

// Scratch offsets (floats)
#define OFF_V2V     0u            // 8192*512
#define OFF_V2A     4194304u      // 16384*512
#define OFF_V1V     12582912u     // 128*512
#define OFF_V1A     12648448u     // 128*512
#define OFF_V1C     12713984u     // 128*512
#define OFF_CTXV    12779520u     // 128*1024
#define OFF_CTXA    12910592u     // 128*512
#define OFF_ALLCTX  12976128u     // 128*2*512
#define OFF_V2C     13107200u     // 256*512
#define OFF_X       13238272u     // 128*1024
#define OFF_GATES   13369344u     // 128*4096
#define OFF_H       13893632u     // 128*1024
#define SCRATCH_FLOATS 14024704u

__device__ float g_scratch[SCRATCH_FLOATS];

__device__ __forceinline__ uint32_t f2tf(float f) {
    uint32_t u;
    asm("cvt.rna.tf32.f32 %0, %1;" : "=r"(u) : "f"(f));
    return u;
}

// ---------------------------------------------------------------------------
// TF32 tensor-core GEMM core:  C[M,N] (+)= A[M,K] @ B[N,K]^T (+ bias[n])
// Tile 64x64x32, 128 threads = 4 warps (2x2), warp tile 32x32.
// Requires M % 64 == 0, K % 32 == 0, lda/ldb % 4 == 0. N ragged-guarded.
// ---------------------------------------------------------------------------
__device__ __forceinline__ void gemm_core(
    const float* __restrict__ A, int lda,
    const float* __restrict__ B, int ldb,
    const float* __restrict__ bias,
    float* __restrict__ C, int ldc,
    int N, int K, int accum,
    int mBase, int nBase,
    uint32_t (*As)[36], uint32_t (*Bs)[36])
{
    const int tid  = threadIdx.x;
    const int lane = tid & 31;
    const int warp = tid >> 5;
    const int wm = warp >> 1;
    const int wn = warp & 1;

    const int lr = tid >> 3;          // 0..15
    const int lc = tid & 7;           // 0..7 (float4 column)

    float acc[2][4][4];
#pragma unroll
    for (int i = 0; i < 2; i++)
#pragma unroll
        for (int j = 0; j < 4; j++)
#pragma unroll
            for (int k = 0; k < 4; k++) acc[i][j][k] = 0.f;

    const int nk = K >> 5;
    float4 pa[4], pb[4];

    {
        const float* Ap = A + (size_t)(mBase + lr) * lda + (lc << 2);
#pragma unroll
        for (int i = 0; i < 4; i++)
            pa[i] = *(const float4*)(Ap + (size_t)(i * 16) * lda);
#pragma unroll
        for (int i = 0; i < 4; i++) {
            const int nr = nBase + lr + i * 16;
            pb[i] = (nr < N) ? *(const float4*)(B + (size_t)nr * ldb + (lc << 2))
                             : make_float4(0.f, 0.f, 0.f, 0.f);
        }
    }
#pragma unroll
    for (int i = 0; i < 4; i++) {
        const int r = lr + (i << 4);
        uint4 v;
        v.x = f2tf(pa[i].x); v.y = f2tf(pa[i].y); v.z = f2tf(pa[i].z); v.w = f2tf(pa[i].w);
        *(uint4*)&As[r][lc << 2] = v;
        uint4 w;
        w.x = f2tf(pb[i].x); w.y = f2tf(pb[i].y); w.z = f2tf(pb[i].z); w.w = f2tf(pb[i].w);
        *(uint4*)&Bs[r][lc << 2] = w;
    }

    for (int kt = 0; kt < nk; kt++) {
        __syncthreads();

        const bool more = (kt + 1 < nk);
        if (more) {
            const int ko = (kt + 1) << 5;
            const float* Ap = A + (size_t)(mBase + lr) * lda + ko + (lc << 2);
#pragma unroll
            for (int i = 0; i < 4; i++)
                pa[i] = *(const float4*)(Ap + (size_t)(i * 16) * lda);
#pragma unroll
            for (int i = 0; i < 4; i++) {
                const int nr = nBase + lr + i * 16;
                pb[i] = (nr < N)
                    ? *(const float4*)(B + (size_t)nr * ldb + ko + (lc << 2))
                    : make_float4(0.f, 0.f, 0.f, 0.f);
            }
        }

#pragma unroll
        for (int kk = 0; kk < 32; kk += 8) {
            uint32_t a[2][4], b[4][2];
#pragma unroll
            for (int im = 0; im < 2; im++) {
                const int r = (wm << 5) + (im << 4) + (lane >> 2);
                const int c = kk + (lane & 3);
                a[im][0] = As[r][c];
                a[im][1] = As[r + 8][c];
                a[im][2] = As[r][c + 4];
                a[im][3] = As[r + 8][c + 4];
            }
#pragma unroll
            for (int jn = 0; jn < 4; jn++) {
                const int nr = (wn << 5) + (jn << 3) + (lane >> 2);
                const int c = kk + (lane & 3);
                b[jn][0] = Bs[nr][c];
                b[jn][1] = Bs[nr][c + 4];
            }
#pragma unroll
            for (int im = 0; im < 2; im++)
#pragma unroll
                for (int jn = 0; jn < 4; jn++)
                    asm volatile(
                        "mma.sync.aligned.m16n8k8.row.col.f32.tf32.tf32.f32 "
                        "{%0,%1,%2,%3}, {%4,%5,%6,%7}, {%8,%9}, {%0,%1,%2,%3};"
                        : "+f"(acc[im][jn][0]), "+f"(acc[im][jn][1]),
                          "+f"(acc[im][jn][2]), "+f"(acc[im][jn][3])
                        : "r"(a[im][0]), "r"(a[im][1]), "r"(a[im][2]), "r"(a[im][3]),
                          "r"(b[jn][0]), "r"(b[jn][1]));
        }

        __syncthreads();
        if (more) {
#pragma unroll
            for (int i = 0; i < 4; i++) {
                const int r = lr + (i << 4);
                uint4 v;
                v.x = f2tf(pa[i].x); v.y = f2tf(pa[i].y); v.z = f2tf(pa[i].z); v.w = f2tf(pa[i].w);
                *(uint4*)&As[r][lc << 2] = v;
                uint4 w;
                w.x = f2tf(pb[i].x); w.y = f2tf(pb[i].y); w.z = f2tf(pb[i].z); w.w = f2tf(pb[i].w);
                *(uint4*)&Bs[r][lc << 2] = w;
            }
        }
    }

#pragma unroll
    for (int im = 0; im < 2; im++) {
        const int m0 = mBase + (wm << 5) + (im << 4) + (lane >> 2);
#pragma unroll
        for (int jn = 0; jn < 4; jn++) {
            const int n0 = nBase + (wn << 5) + (jn << 3) + ((lane & 3) << 1);
#pragma unroll
            for (int half = 0; half < 2; half++) {
                const int m = m0 + half * 8;
                const float v0 = acc[im][jn][half * 2 + 0];
                const float v1 = acc[im][jn][half * 2 + 1];
                if (n0 < N) {
                    float x = v0 + (bias ? bias[n0] : 0.f);
                    if (accum) C[(size_t)m * ldc + n0] += x;
                    else       C[(size_t)m * ldc + n0]  = x;
                }
                if (n0 + 1 < N) {
                    float x = v1 + (bias ? bias[n0 + 1] : 0.f);
                    if (accum) C[(size_t)m * ldc + n0 + 1] += x;
                    else       C[(size_t)m * ldc + n0 + 1]  = x;
                }
            }
        }
    }
}

// ---------------------------------------------------------------------------
// Grouped GEMM: several independent GEMMs in one launch (flat grid,
// per-group block ranges via prefix-sum 'end').
// ---------------------------------------------------------------------------
struct GemmGroup {
    const float* A; const float* B; const float* bias; float* C;
    int lda, ldb, ldc, N, K, accum, nbx, end;
};
struct GemmList { GemmGroup g[6]; int n; };

__global__ void __launch_bounds__(128) gemm_grouped(GemmList L)
{
    __shared__ uint32_t As[64][36];
    __shared__ uint32_t Bs[64][36];

    const int bid = blockIdx.x;
    int gi = 0;
#pragma unroll
    for (int i = 0; i < 6; i++)
        if (i < L.n && bid >= L.g[i].end) gi = i + 1;
    const GemmGroup& G = L.g[gi];
    const int start = gi ? L.g[gi - 1].end : 0;
    const int lb = bid - start;
    const int by = lb / G.nbx;
    const int bx = lb - by * G.nbx;

    gemm_core(G.A, G.lda, G.B, G.ldb, G.bias, G.C, G.ldc,
              G.N, G.K, G.accum, by << 6, bx << 6, As, Bs);
}

// ---------------------------------------------------------------------------
// Both Bahdanau attentions in one launch: block 0..127 visual, 128..255 audio.
// ---------------------------------------------------------------------------
struct AttParams {
    const float* v1; const float* v2; const float* W3; const float* enc;
    float* ctx; int T, C, E;
};

__global__ void __launch_bounds__(256) attend_both(AttParams P0, AttParams P1)
{
    const AttParams P = (blockIdx.x >> 7) ? P1 : P0;
    const int b = blockIdx.x & 127;
    const int tid = threadIdx.x;
    const int warp = tid >> 5, lane = tid & 31;
    __shared__ float s_sc[128];
    __shared__ float s_inv;

    const int T = P.T, C = P.C, E = P.E;
    const float* v1b = P.v1 + (size_t)b * C;
    const float* v2b = P.v2 + (size_t)b * T * C;

    for (int t = warp; t < T; t += 8) {
        const float* row = v2b + (size_t)t * C;
        float acc = 0.f;
        for (int c = lane; c < C; c += 32)
            acc += tanhf(v1b[c] + row[c]) * P.W3[c];
#pragma unroll
        for (int o = 16; o; o >>= 1) acc += __shfl_xor_sync(0xffffffffu, acc, o);
        if (lane == 0) s_sc[t] = acc;
    }
    __syncthreads();

    if (tid == 0) {
        float m = -1e30f;
        for (int t = 0; t < T; t++) m = fmaxf(m, s_sc[t]);
        float s = 0.f;
        for (int t = 0; t < T; t++) { float e = expf(s_sc[t] - m); s_sc[t] = e; s += e; }
        s_inv = 1.f / s;
    }
    __syncthreads();
    const float inv = s_inv;

    const float* encb = P.enc + (size_t)b * T * E;
    for (int e = tid; e < E; e += 256) {
        float acc = 0.f;
        for (int t = 0; t < T; t++) acc += s_sc[t] * encb[(size_t)t * E + e];
        P.ctx[(size_t)b * E + e] = acc * inv;
    }
}

// ---------------------------------------------------------------------------
// Cross-modal attention (T=2) + final context + x = [input, tanh(final_ctx)]
// ---------------------------------------------------------------------------
__global__ void __launch_bounds__(256) ca_finish_kernel(
    const float* __restrict__ v1c,    // [B,512]
    const float* __restrict__ v2c,    // [B*2,512]
    const float* __restrict__ W3,     // [512]
    const float* __restrict__ allctx, // [B,2,512]
    const float* __restrict__ inp,    // [B,512]
    float* __restrict__ x)            // [B,1024]
{
    const int C = 512, EMB = 512;
    const int b = blockIdx.x;
    const int tid = threadIdx.x;
    const int warp = tid >> 5, lane = tid & 31;
    __shared__ float red0[8], red1[8];
    __shared__ float s_a0, s_a1;

    const float* v1b = v1c + (size_t)b * C;
    const float* v20 = v2c + (size_t)(2 * b) * C;
    const float* v21 = v20 + C;

    float p0 = 0.f, p1 = 0.f;
    for (int c = tid; c < C; c += 256) {
        const float w = W3[c];
        p0 += tanhf(v1b[c] + v20[c]) * w;
        p1 += tanhf(v1b[c] + v21[c]) * w;
    }
#pragma unroll
    for (int o = 16; o; o >>= 1) {
        p0 += __shfl_xor_sync(0xffffffffu, p0, o);
        p1 += __shfl_xor_sync(0xffffffffu, p1, o);
    }
    if (lane == 0) { red0[warp] = p0; red1[warp] = p1; }
    __syncthreads();
    if (tid == 0) {
        float s0 = 0.f, s1 = 0.f;
        for (int w = 0; w < 8; w++) { s0 += red0[w]; s1 += red1[w]; }
        const float m = fmaxf(s0, s1);
        const float e0 = expf(s0 - m), e1 = expf(s1 - m);
        const float inv = 1.f / (e0 + e1);
        s_a0 = e0 * inv; s_a1 = e1 * inv;
    }
    __syncthreads();
    const float a0 = s_a0, a1 = s_a1;

    const float* ctx0 = allctx + (size_t)b * 2 * C;
    const float* ctx1 = ctx0 + C;
    float* xb = x + (size_t)b * (EMB + C);
    const float* ib = inp + (size_t)b * EMB;
    for (int e = tid; e < EMB; e += 256) xb[e] = ib[e];
    for (int c = tid; c < C; c += 256)
        xb[EMB + c] = tanhf(a0 * ctx0[c] + a1 * ctx1[c]);
}

// ---------------------------------------------------------------------------
// LSTM pointwise: gates[B,4H] (+ biases) -> h_new, c_new
// ---------------------------------------------------------------------------
__global__ void __launch_bounds__(256) lstm_kernel(
    const float* __restrict__ gates,
    const float* __restrict__ b_ih, const float* __restrict__ b_hh,
    const float* __restrict__ c0,
    float* __restrict__ h_scratch,
    float* __restrict__ h_out, float* __restrict__ c_out)
{
    const int idx = blockIdx.x * 256 + threadIdx.x;
    const int b = idx >> 10, k = idx & 1023;
    const float* g = gates + (size_t)b * 4096;

    const float ig = g[k]        + b_ih[k]        + b_hh[k];
    const float fg = g[1024 + k] + b_ih[1024 + k] + b_hh[1024 + k];
    const float gg = g[2048 + k] + b_ih[2048 + k] + b_hh[2048 + k];
    const float og = g[3072 + k] + b_ih[3072 + k] + b_hh[3072 + k];

    const float si = 1.f / (1.f + expf(-ig));
    const float sf = 1.f / (1.f + expf(-fg));
    const float so = 1.f / (1.f + expf(-og));
    const float cn = sf * c0[idx] + si * tanhf(gg);
    const float hn = so * tanhf(cn);

    h_scratch[idx] = hn;
    h_out[idx] = hn;
    c_out[idx] = cn;
}

// ---------------------------------------------------------------------------
// Launch
// ---------------------------------------------------------------------------
static inline GemmGroup mkgrp(const float* A, int lda, const float* B, int ldb,
                              const float* bias, float* C, int ldc,
                              int M, int N, int K, int accum, int prevEnd)
{
    GemmGroup g;
    g.A = A; g.B = B; g.bias = bias; g.C = C;
    g.lda = lda; g.ldb = ldb; g.ldc = ldc;
    g.N = N; g.K = K; g.accum = accum;
    g.nbx = (N + 63) / 64;
    g.end = prevEnd + g.nbx * (M / 64);
    return g;
}

extern "C" void kernel_launch(void* const* d_in, const int* in_sizes, int n_in,
                              void* d_out, int out_size)
{
    (void)in_sizes; (void)n_in; (void)out_size;

    float* S = nullptr;
    cudaGetSymbolAddress((void**)&S, g_scratch);

    const float* input  = (const float*)d_in[0];
    const float* enc_v  = (const float*)d_in[1];
    const float* enc_a  = (const float*)d_in[2];
    const float* h0     = (const float*)d_in[3];
    const float* c0     = (const float*)d_in[4];
    const float* W_va1  = (const float*)d_in[5];
    const float* W_va2  = (const float*)d_in[6];
    const float* W_va3  = (const float*)d_in[7];
    const float* W_venc = (const float*)d_in[8];
    const float* W_aa1  = (const float*)d_in[9];
    const float* W_aa2  = (const float*)d_in[10];
    const float* W_aa3  = (const float*)d_in[11];
    const float* W_aenc = (const float*)d_in[12];
    const float* W_ca1  = (const float*)d_in[13];
    const float* W_ca2  = (const float*)d_in[14];
    const float* W_ca3  = (const float*)d_in[15];
    const float* W_ih   = (const float*)d_in[16];
    const float* W_hh   = (const float*)d_in[17];
    const float* b_ih   = (const float*)d_in[18];
    const float* b_hh   = (const float*)d_in[19];
    const float* W_out  = (const float*)d_in[20];
    const float* b_out  = (const float*)d_in[21];

    float* out    = (float*)d_out;
    float* logits = out;
    float* h_out  = out + 128 * 20000;
    float* c_out  = h_out + 128 * 1024;

    float* v2v    = S + OFF_V2V;
    float* v2a    = S + OFF_V2A;
    float* v1v    = S + OFF_V1V;
    float* v1a    = S + OFF_V1A;
    float* v1c    = S + OFF_V1C;
    float* ctxv   = S + OFF_CTXV;
    float* ctxa   = S + OFF_CTXA;
    float* allctx = S + OFF_ALLCTX;
    float* v2c    = S + OFF_V2C;
    float* x      = S + OFF_X;
    float* gates  = S + OFF_GATES;
    float* hsc    = S + OFF_H;

    // ---- launch 1: everything that depends only on inputs ----
    GemmList L1; L1.n = 6;
    L1.g[0] = mkgrp(enc_a, 512,  W_aa2, 512,  nullptr, v2a,   512,  16384, 512,  512,  0, 0);
    L1.g[1] = mkgrp(enc_v, 1024, W_va2, 1024, nullptr, v2v,   512,  8192,  512,  1024, 0, L1.g[0].end);
    L1.g[2] = mkgrp(h0,    1024, W_hh,  1024, nullptr, gates, 4096, 128,   4096, 1024, 0, L1.g[1].end);
    L1.g[3] = mkgrp(h0,    1024, W_va1, 1024, nullptr, v1v,   512,  128,   512,  1024, 0, L1.g[2].end);
    L1.g[4] = mkgrp(h0,    1024, W_aa1, 1024, nullptr, v1a,   512,  128,   512,  1024, 0, L1.g[3].end);
    L1.g[5] = mkgrp(h0,    1024, W_ca1, 1024, nullptr, v1c,   512,  128,   512,  1024, 0, L1.g[4].end);
    gemm_grouped<<<L1.g[5].end, 128>>>(L1);

    // ---- launch 2: both attentions ----
    AttParams Pv{v1v, v2v, W_va3, enc_v, ctxv, 64, 512, 1024};
    AttParams Pa{v1a, v2a, W_aa3, enc_a, ctxa, 128, 512, 512};
    attend_both<<<256, 256>>>(Pv, Pa);

    // ---- launch 3: vc/ac projections (interleaved into allctx[B,2,C]) ----
    GemmList L2; L2.n = 2;
    L2.g[0] = mkgrp(ctxv, 1024, W_venc, 1024, nullptr, allctx,       1024, 128, 512, 1024, 0, 0);
    L2.g[1] = mkgrp(ctxa, 512,  W_aenc, 512,  nullptr, allctx + 512, 1024, 128, 512, 512,  0, L2.g[0].end);
    gemm_grouped<<<L2.g[1].end, 128>>>(L2);

    // ---- launch 4: cross-modal v2 over stacked context rows ----
    GemmList L3; L3.n = 1;
    L3.g[0] = mkgrp(allctx, 512, W_ca2, 512, nullptr, v2c, 512, 256, 512, 512, 0, 0);
    gemm_grouped<<<L3.g[0].end, 128>>>(L3);

    // ---- launch 5: 2-way softmax + final context + x ----
    ca_finish_kernel<<<128, 256>>>(v1c, v2c, W_ca3, allctx, input, x);

    // ---- launch 6: x @ W_ih^T accumulated into gates ----
    GemmList L4; L4.n = 1;
    L4.g[0] = mkgrp(x, 1024, W_ih, 1024, nullptr, gates, 4096, 128, 4096, 1024, 1, 0);
    gemm_grouped<<<L4.g[0].end, 128>>>(L4);

    // ---- launch 7: LSTM pointwise ----
    lstm_kernel<<<512, 256>>>(gates, b_ih, b_hh, c0, hsc, h_out, c_out);

    // ---- launch 8: logits ----
    GemmList L5; L5.n = 1;
    L5.g[0] = mkgrp(hsc, 1024, W_out, 1024, b_out, logits, 20000, 128, 20000, 1024, 0, 0);
    gemm_grouped<<<L5.g[0].end, 128>>>(L5);
}